// round 15
// baseline (speedup 1.0000x reference)
#include <cuda_runtime.h>
#include <cuda_fp16.h>
#include <math.h>
#include <stdint.h>

// Problem constants
#define NN 1024
#define TT 64
#define BB 32
#define DD 64
#define FT 64
#define BT 2048
#define NCH 5
#define WCOLS (NCH*TT*FT)   // 20480

// ---------------- scratch (device globals) ---------------------------------
__device__ float g_Xbuf[NN*BT];            // X / X2 node-major fp32 (Y2 sub)
__device__ float g_Wmod[DD*WCOLS];
__device__ float g_Obuf[NN*BB*FT];         // contraction out; EET temp in prologue
__device__ float g_bias[NN*FT];
// fp16 planes
__device__ __half g_XH[NN*BT];             // X node-major hi
__device__ __half g_YH[4*NN*BT];           // Y1_0,Y1_1,Y2_0,Y2_1 node-major hi
__device__ __half g_SH[2048*1024];         // S hi (rows 0-1023 = S_adapt, 1024-2047 = A)
__device__ __half g_BH[2048*1024];         // X^T hi
__device__ __half g_YTH[2*2048*1024];      // Y1^T hi per g
__device__ __half g_EH[1024*64];
__device__ __half g_WTH[WCOLS*64];
__device__ __half g_WbH[(size_t)NN*WCOLS]; // per-node W hi, [n][o*320+ch*64+t]

// ---------------- helpers ---------------------------------------------------
__device__ __forceinline__ uint32_t s2u(const void* p){
    uint32_t a;
    asm("{ .reg .u64 t; cvta.to.shared.u64 t, %1; cvt.u32.u64 %0, t; }" : "=r"(a) : "l"(p));
    return a;
}
__device__ __forceinline__ void cp16(uint32_t s, const void* g){
    asm volatile("cp.async.cg.shared.global [%0], [%1], 16;" :: "r"(s), "l"(g));
}
__device__ __forceinline__ void ldsm4(uint32_t* r, uint32_t a){
    asm volatile("ldmatrix.sync.aligned.m8n8.x4.shared.b16 {%0,%1,%2,%3}, [%4];"
        : "=r"(r[0]), "=r"(r[1]), "=r"(r[2]), "=r"(r[3]) : "r"(a));
}
__device__ __forceinline__ void mma16816(float* d, const uint32_t* a, uint32_t b0, uint32_t b1){
    asm volatile("mma.sync.aligned.m16n8k16.row.col.f32.f16.f16.f32 "
        "{%0,%1,%2,%3}, {%4,%5,%6,%7}, {%8,%9}, {%0,%1,%2,%3};"
        : "+f"(d[0]), "+f"(d[1]), "+f"(d[2]), "+f"(d[3])
        : "r"(a[0]), "r"(a[1]), "r"(a[2]), "r"(a[3]), "r"(b0), "r"(b1));
}
__device__ __forceinline__ uint32_t packh(float v){
    return (uint32_t)__half_as_ushort(__float2half_rn(v));
}
__device__ __forceinline__ uint32_t packh2(float a, float b){
    return (uint32_t)__half_as_ushort(__float2half_rn(a))
         | ((uint32_t)__half_as_ushort(__float2half_rn(b)) << 16);
}

// ============ single-segment fp16 GEMM ======================================
// CTA tile 128x128, 8 warps (4x2), warp tile 32x64, 3-stage cp.async.
// outH!=null: fp16 out (staged, coalesced), supports sub (fp32) + Cbat z-batch.
// outH==null: fp32 C out. tpH: transposed fp16 planes (ldc==2048 layout).
__global__ void __launch_bounds__(256,2) gemm_mma_k(
    const __half* __restrict__ Ah, const __half* __restrict__ Bh,
    float* __restrict__ C, const float* __restrict__ sub,
    float alpha, int Kdim, int kTiles, int ldc,
    int AzRows, long Bbat, long Cbat,
    __half* __restrict__ tpH, __half* __restrict__ outH)
{
    extern __shared__ __align__(16) char smraw[];
    const uint32_t sA = s2u(smraw);              // 3 stages x (16KB A + 16KB B)
    const uint32_t sB = sA + 3*16384;

    const int tid  = threadIdx.x;
    const int wid  = tid >> 5;
    const int lane = tid & 31;
    const int wm   = wid >> 1;
    const int wn   = wid & 1;

    const long aRow0 = (long)blockIdx.z*AzRows + (long)blockIdx.y*128;
    const __half* A0h = Ah + aRow0*Kdim;
    const __half* B0h = Bh + (long)blockIdx.z*Bbat + (long)blockIdx.x*128*Kdim;

    float acc[2][8][4];
#pragma unroll
    for (int i=0;i<2;i++)
#pragma unroll
        for (int j=0;j<8;j++)
#pragma unroll
            for (int q=0;q<4;q++) acc[i][j][q]=0.f;

    const int lrow = tid >> 3;
    const int lc   = tid & 7;
    const int iters = kTiles;

#pragma unroll 1
    for (int kt = 0; kt < iters+2; kt++){
        if (kt < iters){
            const int k0  = kt * 64;
            const int buf = kt % 3;
            const uint32_t da = sA + buf*16384;
            const uint32_t db = sB + buf*16384;
#pragma unroll
            for (int i = 0; i < 4; i++){
                const int row = lrow + i*32;
                const uint32_t o = (uint32_t)row*128 + (uint32_t)((lc ^ (row & 7))*16);
                cp16(da + o, A0h + (long)row*Kdim + k0 + lc*8);
                cp16(db + o, B0h + (long)row*Kdim + k0 + lc*8);
            }
            asm volatile("cp.async.commit_group;" ::: "memory");
        }
        if (kt < 2) continue;
        if (kt < iters)        asm volatile("cp.async.wait_group 2;" ::: "memory");
        else if (kt == iters)  asm volatile("cp.async.wait_group 1;" ::: "memory");
        else                   asm volatile("cp.async.wait_group 0;" ::: "memory");
        __syncthreads();

        const int cbuf = (kt-2) % 3;
        const uint32_t ca = sA + cbuf*16384;
        const uint32_t cb = sB + cbuf*16384;
#pragma unroll
        for (int ks = 0; ks < 4; ks++){
            const int kc = ks*2;
            uint32_t af[2][4], bf[4][4];
#pragma unroll
            for (int mi = 0; mi < 2; mi++){
                const int row = wm*32 + mi*16 + (lane & 15);
                const int c   = kc + (lane >> 4);
                ldsm4(af[mi], ca + row*128 + ((c ^ (row & 7))*16));
            }
#pragma unroll
            for (int ni = 0; ni < 4; ni++){
                const int row = wn*64 + ni*16 + (lane & 15);
                const int c   = kc + (lane >> 4);
                ldsm4(bf[ni], cb + row*128 + ((c ^ (row & 7))*16));
            }
#pragma unroll
            for (int mi = 0; mi < 2; mi++)
#pragma unroll
                for (int ni = 0; ni < 4; ni++){
                    mma16816(acc[mi][ni*2+0], af[mi], bf[ni][0], bf[ni][2]);
                    mma16816(acc[mi][ni*2+1], af[mi], bf[ni][1], bf[ni][3]);
                }
        }
        __syncthreads();
    }

    if (outH){
        // staged fp16 output: 4 passes of 32 rows, coalesced u32 row writes
        __half* Op = outH + Cbat*blockIdx.z;
        uint32_t* Cs = (uint32_t*)smraw;          // 32 x 65 u32
#pragma unroll 1
        for (int pass = 0; pass < 4; pass++){
            __syncthreads();
            if (wm == pass){
#pragma unroll
                for (int mi = 0; mi < 2; mi++){
                    const int r0 = mi*16 + (lane >> 2);
                    const long gr = (long)blockIdx.y*128 + pass*32 + r0;
#pragma unroll
                    for (int ni = 0; ni < 8; ni++){
                        const int cu = wn*32 + ni*4 + (lane & 3);
                        float v0 = alpha*acc[mi][ni][0], v1 = alpha*acc[mi][ni][1];
                        float v2 = alpha*acc[mi][ni][2], v3 = alpha*acc[mi][ni][3];
                        if (sub){
                            const long gc = (long)blockIdx.x*128 + cu*2;
                            v0 -= sub[gr*ldc + gc];     v1 -= sub[gr*ldc + gc + 1];
                            v2 -= sub[(gr+8)*ldc + gc]; v3 -= sub[(gr+8)*ldc + gc + 1];
                        }
                        Cs[r0*65 + cu]     = packh2(v0, v1);
                        Cs[(r0+8)*65 + cu] = packh2(v2, v3);
                    }
                }
            }
            __syncthreads();
#pragma unroll
            for (int q2 = 0; q2 < 8; q2++){
                const int idx = q2*256 + tid;
                const int row = idx >> 6, cu = idx & 63;
                *(uint32_t*)(Op + ((long)blockIdx.y*128 + pass*32 + row)*ldc
                             + (long)blockIdx.x*128 + cu*2) = Cs[row*65 + cu];
            }
        }
    } else {
        const long rb = (long)blockIdx.y*128 + wm*32 + (lane >> 2);
        const long cbase = (long)blockIdx.x*128 + wn*64 + (lane & 3)*2;
        float* Cp = C + Cbat*blockIdx.z;
#pragma unroll
        for (int mi = 0; mi < 2; mi++)
#pragma unroll
            for (int ni = 0; ni < 8; ni++){
                const long r = rb + mi*16;
                const long cc = cbase + ni*8;
                float2 v0, v1;
                v0.x = alpha*acc[mi][ni][0]; v0.y = alpha*acc[mi][ni][1];
                v1.x = alpha*acc[mi][ni][2]; v1.y = alpha*acc[mi][ni][3];
                if (sub){
                    v0.x -= sub[r*ldc + cc];     v0.y -= sub[r*ldc + cc + 1];
                    v1.x -= sub[(r+8)*ldc + cc]; v1.y -= sub[(r+8)*ldc + cc + 1];
                }
                *(float2*)(Cp + r*ldc + cc)     = v0;
                *(float2*)(Cp + (r+8)*ldc + cc) = v1;
            }
    }

    // ---- optional transposed fp16-hi output ----
    if (tpH){
        uint32_t* Cs = (uint32_t*)smraw;
        const int g     = (blockIdx.y*128) >> 10;
        const int node0 = (blockIdx.y*128) & 1023;
        const int bt0   = blockIdx.x*128;
        const long gpl  = (long)g * 2048 * 1024;
        const int ct = tid >> 1;
        const int rh = (tid & 1) * 16;
#pragma unroll 1
        for (int pass = 0; pass < 4; pass++){
            __syncthreads();
            if (wm == pass){
#pragma unroll
                for (int mi = 0; mi < 2; mi++){
                    const int r0 = mi*16 + (lane >> 2);
#pragma unroll
                    for (int ni = 0; ni < 8; ni++){
                        const int c0 = wn*64 + ni*8 + (lane & 3)*2;
                        Cs[r0*132 + c0]       = packh(alpha*acc[mi][ni][0]);
                        Cs[r0*132 + c0+1]     = packh(alpha*acc[mi][ni][1]);
                        Cs[(r0+8)*132 + c0]   = packh(alpha*acc[mi][ni][2]);
                        Cs[(r0+8)*132 + c0+1] = packh(alpha*acc[mi][ni][3]);
                    }
                }
            }
            __syncthreads();
            uint32_t hi[8];
#pragma unroll
            for (int i = 0; i < 16; i += 2){
                uint32_t w0 = Cs[(rh+i)*132 + ct];
                uint32_t w1 = Cs[(rh+i+1)*132 + ct];
                hi[i>>1] = (w0 & 0xffffu) | (w1 << 16);
            }
            const long go = gpl + (long)(bt0 + ct)*1024 + node0 + pass*32 + rh;
            *(uint4*)(tpH + go)     = make_uint4(hi[0],hi[1],hi[2],hi[3]);
            *(uint4*)(tpH + go + 8) = make_uint4(hi[4],hi[5],hi[6],hi[7]);
        }
    }
}

// ============ per-node contraction, all-fp16 A via cp.async =================
// O[n][b][o] = sum_{ch,t} A5[n][b][ch*64+t] * Wb[n][o][ch*64+t] + bias[n][o]
__global__ void __launch_bounds__(128,3) contract_mma_k(
    const __half* __restrict__ XH, const __half* __restrict__ YH,
    const __half* __restrict__ WbH,
    const float* __restrict__ bias, float* __restrict__ O)
{
    extern __shared__ __align__(16) char sm[];
    const uint32_t aH = s2u(sm);           // A: 5ch x 32b x 128B = 20KB
    const uint32_t bB = aH + 20480;        // B: 2 stages x 8KB

    const int n = blockIdx.x;
    const int tid = threadIdx.x;
    const int w = tid >> 5;
    const int lane = tid & 31;

    // A channels via cp.async (group 0, together with B ch0)
    const __half* XHn = XH + (long)n*2048;
#pragma unroll
    for (int i = 0; i < 10; i++){
        int u = i*128 + tid;
        int ch = u >> 8, rem = u & 255, b = rem >> 3, q = rem & 7;
        const __half* src = (ch==0 ? XHn
                                   : YH + ((long)(ch-1)*1024 + n)*2048) + b*64 + q*8;
        cp16(aH + (uint32_t)(ch*4096 + b*128 + ((q ^ (b&7))*16)), src);
    }
    const __half* WH = WbH + (long)n*WCOLS;
#pragma unroll
    for (int i = 0; i < 4; i++){
        int u = i*128 + tid, o = u >> 3, q = u & 7;
        cp16(bB + (uint32_t)(o*128 + ((q ^ (o&7))*16)), WH + o*320 + q*8);
    }
    asm volatile("cp.async.commit_group;" ::: "memory");

    float acc[2][2][4];
#pragma unroll
    for (int a0=0;a0<2;a0++)
#pragma unroll
        for (int a1=0;a1<2;a1++)
#pragma unroll
            for (int a2=0;a2<4;a2++) acc[a0][a1][a2]=0.f;

#pragma unroll 1
    for (int ch = 0; ch < 5; ch++){
        if (ch < 4){
            const int s = (ch+1) & 1;
#pragma unroll
            for (int i = 0; i < 4; i++){
                int u = i*128 + tid, o = u >> 3, q = u & 7;
                cp16(bB + (uint32_t)(s*8192 + o*128 + ((q ^ (o&7))*16)),
                     WH + (ch+1)*64 + o*320 + q*8);
            }
            asm volatile("cp.async.commit_group;" ::: "memory");
            asm volatile("cp.async.wait_group 1;" ::: "memory");
        } else {
            asm volatile("cp.async.wait_group 0;" ::: "memory");
        }
        __syncthreads();

        const uint32_t Bs = bB + (ch & 1)*8192;
        const uint32_t Ach = (uint32_t)(ch*4096);
#pragma unroll
        for (int ks = 0; ks < 4; ks++){
            const int kc = ks*2;
            uint32_t afh[2][4], bfh[4];
#pragma unroll
            for (int mi = 0; mi < 2; mi++){
                const int row = mi*16 + (lane & 15);
                const int c = kc + (lane >> 4);
                ldsm4(afh[mi], aH + Ach + (uint32_t)(row*128 + ((c ^ (row & 7))*16)));
            }
            {
                const int row = w*16 + (lane & 15);
                const int c = kc + (lane >> 4);
                ldsm4(bfh, Bs + (uint32_t)(row*128 + ((c ^ (row & 7))*16)));
            }
#pragma unroll
            for (int mi = 0; mi < 2; mi++){
                mma16816(acc[mi][0], afh[mi], bfh[0], bfh[2]);
                mma16816(acc[mi][1], afh[mi], bfh[1], bfh[3]);
            }
        }
        __syncthreads();
    }

#pragma unroll
    for (int mi = 0; mi < 2; mi++)
#pragma unroll
        for (int n8 = 0; n8 < 2; n8++){
            const int b0 = mi*16 + (lane >> 2);
            const int oc = w*16 + n8*8 + (lane & 3)*2;
            const float bi0 = bias[n*64 + oc];
            const float bi1 = bias[n*64 + oc + 1];
            float2 v0, v1;
            v0.x = acc[mi][n8][0] + bi0; v0.y = acc[mi][n8][1] + bi1;
            v1.x = acc[mi][n8][2] + bi0; v1.y = acc[mi][n8][3] + bi1;
            *(float2*)(O + (long)n*2048 + b0*64 + oc)     = v0;
            *(float2*)(O + (long)n*2048 + (b0+8)*64 + oc) = v1;
        }
}

// ---------------- fp32 -> fp16 hi convert ----------------------------------
__global__ void conv_h(const float* __restrict__ in, __half* __restrict__ oh){
    int idx = blockIdx.x*256 + threadIdx.x;
    oh[idx] = __float2half_rn(in[idx]);
}

// ---------------- transpose, hi fp16 only ----------------------------------
__global__ void tsplit_h(const float* __restrict__ in, __half* __restrict__ oh,
                         int R, int Cc){
    __shared__ float t[32][33];
    int c0 = blockIdx.x*32, r0 = blockIdx.y*32;
    int tx = threadIdx.x, ty = threadIdx.y;
#pragma unroll
    for (int i = 0; i < 32; i += 8)
        t[ty+i][tx] = in[(long)(r0+ty+i)*Cc + c0+tx];
    __syncthreads();
#pragma unroll
    for (int i = 0; i < 32; i += 8)
        oh[(long)(c0+ty+i)*R + r0+tx] = __float2half_rn(t[tx][ty+i]);
}

// ---------------- row softmax of relu(row) -> fp16 hi plane ----------------
__global__ void relu_softmax_k(const float* __restrict__ in,
                               __half* __restrict__ oh){
    const int row = blockIdx.x;
    const int tid = threadIdx.x;
    __shared__ float rowv[1024];
    __shared__ float red[256];
    const float* r = in + (long)row*NN;
    for (int j=tid;j<NN;j+=256) rowv[j] = fmaxf(r[j], 0.f);
    __syncthreads();
    float mx = 0.f;
    for (int j=tid;j<NN;j+=256) mx = fmaxf(mx, rowv[j]);
    red[tid]=mx; __syncthreads();
    for (int s=128;s>0;s>>=1){ if(tid<s) red[tid]=fmaxf(red[tid],red[tid+s]); __syncthreads(); }
    mx = red[0];
    __syncthreads();
    float sum=0.f;
    for (int j=tid;j<NN;j+=256){ float e = expf(rowv[j]-mx); rowv[j]=e; sum+=e; }
    red[tid]=sum; __syncthreads();
    for (int s=128;s>0;s>>=1){ if(tid<s) red[tid]+=red[tid+s]; __syncthreads(); }
    float inv = 1.f/red[0];
    for (int j=tid;j<NN;j+=256)
        oh[(long)row*NN+j] = __float2half_rn(rowv[j]*inv);
}

// ---------------- x[B,N,T] -> X[N,B*T] fp32 + fp16 -------------------------
__global__ void txpose_x_k(const float* __restrict__ x, float* __restrict__ X,
                           __half* __restrict__ XH){
    int idx = blockIdx.x*256 + threadIdx.x;
    float4 v = ((const float4*)x)[((long)((idx>>4)&31)*NN + (idx>>9))*16 + (idx&15)];
    ((float4*)X)[idx] = v;
    uint2 p;
    p.x = packh2(v.x, v.y);
    p.y = packh2(v.z, v.w);
    *(uint2*)(XH + (long)idx*4) = p;
}

// ---------------- gather W -> Wmod [64, 20480], cols = o*320+ch*64+t -------
__global__ void wmod_k(const float* __restrict__ W, float* __restrict__ Wm){
    int idx = blockIdx.x*256 + threadIdx.x;
    if (idx >= DD*WCOLS) return;
    int d = idx / WCOLS;
    int c = idx - d*WCOLS;
    int o = c / 320;
    int r = c - o*320;
    int ch = r >> 6;
    int t = r & 63;
    int to = t*64 + o;
    float val;
    if (ch==0){
        val = W[(long)(d*3)*4096 + to] + W[(long)((64+d)*3)*4096 + to];
    } else {
        int g = (ch-1)&1;
        int k = 1 + ((ch-1)>>1);
        val = W[(long)((g*64+d)*3+k)*4096 + to];
    }
    Wm[idx] = val;
}

// ---------------- bias -----------------------------------------------------
__global__ void bias_k(const float* __restrict__ E, const float* __restrict__ bp,
                       float* __restrict__ bias){
    int n = blockIdx.x, o = threadIdx.x;
    float s = 0.f;
    for (int d=0; d<64; d++) s += E[n*64+d]*(bp[d*64+o] + bp[4096 + d*64+o]);
    bias[n*64+o]=s;
}

// ---------------- layer1 epilogue: LN/relu -> Xb fp32 + XH fp16 ------------
__global__ void proj_ln_relu_k(const float* __restrict__ O, const float* __restrict__ pw,
                               const float* __restrict__ pb, const float* __restrict__ gam,
                               const float* __restrict__ bet, float* __restrict__ Xout,
                               __half* __restrict__ XHout)
{
    const int nb = blockIdx.x;
    const int t = threadIdx.x;
    __shared__ float v[64], r1[64], r2[64];
    v[t] = O[(long)nb*64 + t];
    __syncthreads();
    float h = pb[t];
#pragma unroll
    for (int o=0;o<64;o++) h = fmaf(v[o], pw[o*64+t], h);
    r1[t]=h; r2[t]=h*h; __syncthreads();
    for (int s=32;s>0;s>>=1){ if(t<s){ r1[t]+=r1[t+s]; r2[t]+=r2[t+s]; } __syncthreads(); }
    float m = r1[0]*0.015625f;
    float var = r2[0]*0.015625f - m*m;
    float y = (h-m)*rsqrtf(var+1e-5f)*gam[t]+bet[t];
    y = fmaxf(y,0.f);
    const int n = nb>>5, b = nb&31;
    Xout[(long)n*BT + b*64 + t] = y;
    XHout[(long)n*BT + b*64 + t] = __float2half_rn(y);
}

// ---------------- layer2 epilogue ------------------------------------------
__global__ void final_k(const float* __restrict__ O, const float* __restrict__ pw,
                        const float* __restrict__ pb, const float* __restrict__ x,
                        const float* __restrict__ rg, const float* __restrict__ gam,
                        const float* __restrict__ bet, float* __restrict__ out)
{
    const int nb = blockIdx.x;
    const int t = threadIdx.x;
    const int n = nb>>5, b = nb&31;
    __shared__ float v[64], r1[64], r2[64];
    v[t]=O[(long)nb*64+t];
    __syncthreads();
    float h = pb[t];
#pragma unroll
    for (int o=0;o<64;o++) h = fmaf(v[o], pw[o*64+t], h);
    float sg = 1.f/(1.f+expf(-rg[0]));
    h = fmaf(sg, x[((long)b*NN+n)*64 + t], h);
    r1[t]=h; r2[t]=h*h; __syncthreads();
    for (int s=32;s>0;s>>=1){ if(t<s){ r1[t]+=r1[t+s]; r2[t]+=r2[t+s]; } __syncthreads(); }
    float m=r1[0]*0.015625f, var=r2[0]*0.015625f-m*m;
    out[((long)b*NN+n)*64+t] = (h-m)*rsqrtf(var+1e-5f)*gam[t]+bet[t];
}

// ===========================================================================
extern "C" void kernel_launch(void* const* d_in, const int* in_sizes, int n_in,
                              void* d_out, int out_size)
{
    const float* x     = (const float*)d_in[0];
    const float* A_fix = (const float*)d_in[1];
    const float* E     = (const float*)d_in[2];
    const float* W1    = (const float*)d_in[3];
    const float* b1p   = (const float*)d_in[4];
    const float* W2    = (const float*)d_in[5];
    const float* b2p   = (const float*)d_in[6];
    const float* p1w   = (const float*)d_in[7];
    const float* p1b   = (const float*)d_in[8];
    const float* p2w   = (const float*)d_in[9];
    const float* p2b   = (const float*)d_in[10];
    const float* g1    = (const float*)d_in[11];
    const float* be1   = (const float*)d_in[12];
    const float* g2    = (const float*)d_in[13];
    const float* be2   = (const float*)d_in[14];
    const float* rg    = (const float*)d_in[15];
    float* out = (float*)d_out;

    float *Xb,*Wm,*Ob,*Bi;
    __half *XH,*YH,*SH,*BH,*YTH,*EH,*WTH,*WbH;
    cudaGetSymbolAddress((void**)&Xb,  g_Xbuf);
    cudaGetSymbolAddress((void**)&Wm,  g_Wmod);
    cudaGetSymbolAddress((void**)&Ob,  g_Obuf);
    cudaGetSymbolAddress((void**)&Bi,  g_bias);
    cudaGetSymbolAddress((void**)&XH,  g_XH);
    cudaGetSymbolAddress((void**)&YH,  g_YH);
    cudaGetSymbolAddress((void**)&SH,  g_SH);
    cudaGetSymbolAddress((void**)&BH,  g_BH);
    cudaGetSymbolAddress((void**)&YTH, g_YTH);
    cudaGetSymbolAddress((void**)&EH,  g_EH);
    cudaGetSymbolAddress((void**)&WTH, g_WTH);
    cudaGetSymbolAddress((void**)&WbH, g_WbH);

    cudaFuncSetAttribute(gemm_mma_k, cudaFuncAttributeMaxDynamicSharedMemorySize, 98304);
    cudaFuncSetAttribute(contract_mma_k, cudaFuncAttributeMaxDynamicSharedMemorySize, 36864);
    const int MMSM = 98304;
    const int CTSM = 36864;

    // --- prologue ---
    wmod_k<<<(DD*WCOLS+255)/256,256>>>(W1, Wm);
    tsplit_h<<<dim3(640,2,1),dim3(32,8)>>>(Wm, WTH, 64, WCOLS);
    conv_h<<<(NN*DD)/256,256>>>(E, EH);
    gemm_mma_k<<<dim3(160,8,1),256,MMSM>>>(EH, WTH, nullptr, nullptr, 1.f,
                                           64, 1, WCOLS, 0, 0, 0,
                                           nullptr, WbH);
    gemm_mma_k<<<dim3(8,8,1),256,MMSM>>>(EH, EH, Ob, nullptr, 1.f,
                                         64, 1, 1024, 0, 0, 0,
                                         nullptr, nullptr);
    relu_softmax_k<<<1024,256>>>(Ob,    SH);
    relu_softmax_k<<<1024,256>>>(A_fix, SH + (long)NN*NN);
    txpose_x_k<<<2048,256>>>(x, Xb, XH);
    tsplit_h<<<dim3(64,32,1),dim3(32,8)>>>(Xb, BH, 1024, 2048);
    bias_k<<<1024,64>>>(E, b1p, Bi);

    // --- layer 1 ---
    gemm_mma_k<<<dim3(16,16,1),256,MMSM>>>(SH, BH, nullptr, nullptr, 1.f,
                                           1024, 16, 2048, 0, 0, 0,
                                           YTH, YH);
    gemm_mma_k<<<dim3(16,8,2),256,MMSM>>>(SH, YTH, nullptr, Xb, 2.f,
                                          1024, 16, 2048, 1024, 2048L*1024, 1024L*2048,
                                          nullptr, YH + 2L*NN*BT);
    contract_mma_k<<<1024,128,CTSM>>>(XH, YH, WbH, Bi, Ob);
    proj_ln_relu_k<<<NN*BB,64>>>(Ob, p1w, p1b, g1, be1, Xb, XH);

    // --- layer 2 ---
    wmod_k<<<(DD*WCOLS+255)/256,256>>>(W2, Wm);
    tsplit_h<<<dim3(640,2,1),dim3(32,8)>>>(Wm, WTH, 64, WCOLS);
    gemm_mma_k<<<dim3(160,8,1),256,MMSM>>>(EH, WTH, nullptr, nullptr, 1.f,
                                           64, 1, WCOLS, 0, 0, 0,
                                           nullptr, WbH);
    bias_k<<<1024,64>>>(E, b2p, Bi);
    tsplit_h<<<dim3(64,32,1),dim3(32,8)>>>(Xb, BH, 1024, 2048);
    gemm_mma_k<<<dim3(16,16,1),256,MMSM>>>(SH, BH, nullptr, nullptr, 1.f,
                                           1024, 16, 2048, 0, 0, 0,
                                           YTH, YH);
    gemm_mma_k<<<dim3(16,8,2),256,MMSM>>>(SH, YTH, nullptr, Xb, 2.f,
                                          1024, 16, 2048, 1024, 2048L*1024, 1024L*2048,
                                          nullptr, YH + 2L*NN*BT);
    contract_mma_k<<<1024,128,CTSM>>>(XH, YH, WbH, Bi, Ob);
    final_k<<<NN*BB,64>>>(Ob, p2w, p2b, x, rg, g2, be2, out);
}

// round 16
// speedup vs baseline: 1.2636x; 1.2636x over previous
#include <cuda_runtime.h>
#include <cuda_fp16.h>
#include <math.h>
#include <stdint.h>

// Problem constants
#define NN 1024
#define TT 64
#define BB 32
#define DD 64
#define FT 64
#define BT 2048
#define NCH 5
#define WCOLS (NCH*TT*FT)   // 20480

// ---------------- scratch (device globals) ---------------------------------
__device__ float g_Xbuf[NN*BT];            // X / X2 node-major fp32 (Y2 sub)
__device__ float g_Wmod[DD*WCOLS];
__device__ float g_Obuf[NN*BB*FT];         // contraction out; EET temp in prologue
__device__ float g_bias[NN*FT];
// fp16 planes
__device__ __half g_XH[NN*BT];             // X node-major hi
__device__ __half g_YH[4*NN*BT];           // Y1_0,Y1_1,Y2_0,Y2_1 node-major hi
__device__ __half g_SH[2048*1024];         // S hi (rows 0-1023 = S_adapt, 1024-2047 = A)
__device__ __half g_BH[2048*1024];         // X^T hi
__device__ __half g_YTH[2*2048*1024];      // Y1^T hi per g
__device__ __half g_EH[1024*64];
__device__ __half g_WTH[WCOLS*64];
__device__ __half g_WbH[(size_t)NN*WCOLS]; // per-node W hi, [n][o*320+ch*64+t]

// ---------------- helpers ---------------------------------------------------
__device__ __forceinline__ uint32_t s2u(const void* p){
    uint32_t a;
    asm("{ .reg .u64 t; cvta.to.shared.u64 t, %1; cvt.u32.u64 %0, t; }" : "=r"(a) : "l"(p));
    return a;
}
__device__ __forceinline__ void cp16(uint32_t s, const void* g){
    asm volatile("cp.async.cg.shared.global [%0], [%1], 16;" :: "r"(s), "l"(g));
}
__device__ __forceinline__ void ldsm4(uint32_t* r, uint32_t a){
    asm volatile("ldmatrix.sync.aligned.m8n8.x4.shared.b16 {%0,%1,%2,%3}, [%4];"
        : "=r"(r[0]), "=r"(r[1]), "=r"(r[2]), "=r"(r[3]) : "r"(a));
}
__device__ __forceinline__ void mma16816(float* d, const uint32_t* a, uint32_t b0, uint32_t b1){
    asm volatile("mma.sync.aligned.m16n8k16.row.col.f32.f16.f16.f32 "
        "{%0,%1,%2,%3}, {%4,%5,%6,%7}, {%8,%9}, {%0,%1,%2,%3};"
        : "+f"(d[0]), "+f"(d[1]), "+f"(d[2]), "+f"(d[3])
        : "r"(a[0]), "r"(a[1]), "r"(a[2]), "r"(a[3]), "r"(b0), "r"(b1));
}
__device__ __forceinline__ uint32_t packh(float v){
    return (uint32_t)__half_as_ushort(__float2half_rn(v));
}
__device__ __forceinline__ uint32_t packh2(float a, float b){
    return (uint32_t)__half_as_ushort(__float2half_rn(a))
         | ((uint32_t)__half_as_ushort(__float2half_rn(b)) << 16);
}

// ============ single-segment fp16 GEMM ======================================
// CTA tile 128x128, 8 warps (4x2), warp tile 32x64, 3-stage cp.async.
// outH!=null: DIRECT fp16 out (sub fp32 fused, Cbat z-batch).
// outH==null: fp32 C out. tpH: transposed fp16 planes (ldc==2048 layout).
__global__ void __launch_bounds__(256,2) gemm_mma_k(
    const __half* __restrict__ Ah, const __half* __restrict__ Bh,
    float* __restrict__ C, const float* __restrict__ sub,
    float alpha, int Kdim, int kTiles, int ldc,
    int AzRows, long Bbat, long Cbat,
    __half* __restrict__ tpH, __half* __restrict__ outH)
{
    extern __shared__ __align__(16) char smraw[];
    const uint32_t sA = s2u(smraw);              // 3 stages x (16KB A + 16KB B)
    const uint32_t sB = sA + 3*16384;

    const int tid  = threadIdx.x;
    const int wid  = tid >> 5;
    const int lane = tid & 31;
    const int wm   = wid >> 1;
    const int wn   = wid & 1;

    const long aRow0 = (long)blockIdx.z*AzRows + (long)blockIdx.y*128;
    const __half* A0h = Ah + aRow0*Kdim;
    const __half* B0h = Bh + (long)blockIdx.z*Bbat + (long)blockIdx.x*128*Kdim;

    float acc[2][8][4];
#pragma unroll
    for (int i=0;i<2;i++)
#pragma unroll
        for (int j=0;j<8;j++)
#pragma unroll
            for (int q=0;q<4;q++) acc[i][j][q]=0.f;

    const int lrow = tid >> 3;
    const int lc   = tid & 7;
    const int iters = kTiles;

#pragma unroll 1
    for (int kt = 0; kt < iters+2; kt++){
        if (kt < iters){
            const int k0  = kt * 64;
            const int buf = kt % 3;
            const uint32_t da = sA + buf*16384;
            const uint32_t db = sB + buf*16384;
#pragma unroll
            for (int i = 0; i < 4; i++){
                const int row = lrow + i*32;
                const uint32_t o = (uint32_t)row*128 + (uint32_t)((lc ^ (row & 7))*16);
                cp16(da + o, A0h + (long)row*Kdim + k0 + lc*8);
                cp16(db + o, B0h + (long)row*Kdim + k0 + lc*8);
            }
            asm volatile("cp.async.commit_group;" ::: "memory");
        }
        if (kt < 2) continue;
        if (kt < iters)        asm volatile("cp.async.wait_group 2;" ::: "memory");
        else if (kt == iters)  asm volatile("cp.async.wait_group 1;" ::: "memory");
        else                   asm volatile("cp.async.wait_group 0;" ::: "memory");
        __syncthreads();

        const int cbuf = (kt-2) % 3;
        const uint32_t ca = sA + cbuf*16384;
        const uint32_t cb = sB + cbuf*16384;
#pragma unroll
        for (int ks = 0; ks < 4; ks++){
            const int kc = ks*2;
            uint32_t af[2][4], bf[4][4];
#pragma unroll
            for (int mi = 0; mi < 2; mi++){
                const int row = wm*32 + mi*16 + (lane & 15);
                const int c   = kc + (lane >> 4);
                ldsm4(af[mi], ca + row*128 + ((c ^ (row & 7))*16));
            }
#pragma unroll
            for (int ni = 0; ni < 4; ni++){
                const int row = wn*64 + ni*16 + (lane & 15);
                const int c   = kc + (lane >> 4);
                ldsm4(bf[ni], cb + row*128 + ((c ^ (row & 7))*16));
            }
#pragma unroll
            for (int mi = 0; mi < 2; mi++)
#pragma unroll
                for (int ni = 0; ni < 4; ni++){
                    mma16816(acc[mi][ni*2+0], af[mi], bf[ni][0], bf[ni][2]);
                    mma16816(acc[mi][ni*2+1], af[mi], bf[ni][1], bf[ni][3]);
                }
        }
        __syncthreads();
    }

    const long rb = (long)blockIdx.y*128 + wm*32 + (lane >> 2);
    const long cbase = (long)blockIdx.x*128 + wn*64 + (lane & 3)*2;

    if (outH){
        // direct fp16 stores (R14 style), sub fused
        __half* Op = outH + Cbat*blockIdx.z;
#pragma unroll
        for (int mi = 0; mi < 2; mi++)
#pragma unroll
            for (int ni = 0; ni < 8; ni++){
                const long r = rb + mi*16;
                const long cc = cbase + ni*8;
#pragma unroll
                for (int hf = 0; hf < 2; hf++){
                    const long rr = r + hf*8;
                    float v0 = alpha*acc[mi][ni][hf*2+0];
                    float v1 = alpha*acc[mi][ni][hf*2+1];
                    if (sub){
                        v0 -= sub[rr*ldc + cc];
                        v1 -= sub[rr*ldc + cc + 1];
                    }
                    *(uint32_t*)(Op + rr*ldc + cc) = packh2(v0, v1);
                }
            }
    } else {
        float* Cp = C + Cbat*blockIdx.z;
#pragma unroll
        for (int mi = 0; mi < 2; mi++)
#pragma unroll
            for (int ni = 0; ni < 8; ni++){
                const long r = rb + mi*16;
                const long cc = cbase + ni*8;
                float2 v0, v1;
                v0.x = alpha*acc[mi][ni][0]; v0.y = alpha*acc[mi][ni][1];
                v1.x = alpha*acc[mi][ni][2]; v1.y = alpha*acc[mi][ni][3];
                if (sub){
                    v0.x -= sub[r*ldc + cc];     v0.y -= sub[r*ldc + cc + 1];
                    v1.x -= sub[(r+8)*ldc + cc]; v1.y -= sub[(r+8)*ldc + cc + 1];
                }
                *(float2*)(Cp + r*ldc + cc)     = v0;
                *(float2*)(Cp + (r+8)*ldc + cc) = v1;
            }
    }

    // ---- optional transposed fp16-hi output ----
    if (tpH){
        uint32_t* Cs = (uint32_t*)smraw;
        const int g     = (blockIdx.y*128) >> 10;
        const int node0 = (blockIdx.y*128) & 1023;
        const int bt0   = blockIdx.x*128;
        const long gpl  = (long)g * 2048 * 1024;
        const int ct = tid >> 1;
        const int rh = (tid & 1) * 16;
#pragma unroll 1
        for (int pass = 0; pass < 4; pass++){
            __syncthreads();
            if (wm == pass){
#pragma unroll
                for (int mi = 0; mi < 2; mi++){
                    const int r0 = mi*16 + (lane >> 2);
#pragma unroll
                    for (int ni = 0; ni < 8; ni++){
                        const int c0 = wn*64 + ni*8 + (lane & 3)*2;
                        Cs[r0*132 + c0]       = packh(alpha*acc[mi][ni][0]);
                        Cs[r0*132 + c0+1]     = packh(alpha*acc[mi][ni][1]);
                        Cs[(r0+8)*132 + c0]   = packh(alpha*acc[mi][ni][2]);
                        Cs[(r0+8)*132 + c0+1] = packh(alpha*acc[mi][ni][3]);
                    }
                }
            }
            __syncthreads();
            uint32_t hi[8];
#pragma unroll
            for (int i = 0; i < 16; i += 2){
                uint32_t w0 = Cs[(rh+i)*132 + ct];
                uint32_t w1 = Cs[(rh+i+1)*132 + ct];
                hi[i>>1] = (w0 & 0xffffu) | (w1 << 16);
            }
            const long go = gpl + (long)(bt0 + ct)*1024 + node0 + pass*32 + rh;
            *(uint4*)(tpH + go)     = make_uint4(hi[0],hi[1],hi[2],hi[3]);
            *(uint4*)(tpH + go + 8) = make_uint4(hi[4],hi[5],hi[6],hi[7]);
        }
    }
}

// ============ per-node contraction, all-fp16 A via cp.async =================
// O[n][b][o] = sum_{ch,t} A5[n][b][ch*64+t] * Wb[n][o][ch*64+t] + bias[n][o]
__global__ void __launch_bounds__(128,3) contract_mma_k(
    const __half* __restrict__ XH, const __half* __restrict__ YH,
    const __half* __restrict__ WbH,
    const float* __restrict__ bias, float* __restrict__ O)
{
    extern __shared__ __align__(16) char sm[];
    const uint32_t aH = s2u(sm);           // A: 5ch x 32b x 128B = 20KB
    const uint32_t bB = aH + 20480;        // B: 2 stages x 8KB

    const int n = blockIdx.x;
    const int tid = threadIdx.x;
    const int w = tid >> 5;
    const int lane = tid & 31;

    // A channels via cp.async (group 0, together with B ch0)
    const __half* XHn = XH + (long)n*2048;
#pragma unroll
    for (int i = 0; i < 10; i++){
        int u = i*128 + tid;
        int ch = u >> 8, rem = u & 255, b = rem >> 3, q = rem & 7;
        const __half* src = (ch==0 ? XHn
                                   : YH + ((long)(ch-1)*1024 + n)*2048) + b*64 + q*8;
        cp16(aH + (uint32_t)(ch*4096 + b*128 + ((q ^ (b&7))*16)), src);
    }
    const __half* WH = WbH + (long)n*WCOLS;
#pragma unroll
    for (int i = 0; i < 4; i++){
        int u = i*128 + tid, o = u >> 3, q = u & 7;
        cp16(bB + (uint32_t)(o*128 + ((q ^ (o&7))*16)), WH + o*320 + q*8);
    }
    asm volatile("cp.async.commit_group;" ::: "memory");

    float acc[2][2][4];
#pragma unroll
    for (int a0=0;a0<2;a0++)
#pragma unroll
        for (int a1=0;a1<2;a1++)
#pragma unroll
            for (int a2=0;a2<4;a2++) acc[a0][a1][a2]=0.f;

#pragma unroll 1
    for (int ch = 0; ch < 5; ch++){
        if (ch < 4){
            const int s = (ch+1) & 1;
#pragma unroll
            for (int i = 0; i < 4; i++){
                int u = i*128 + tid, o = u >> 3, q = u & 7;
                cp16(bB + (uint32_t)(s*8192 + o*128 + ((q ^ (o&7))*16)),
                     WH + (ch+1)*64 + o*320 + q*8);
            }
            asm volatile("cp.async.commit_group;" ::: "memory");
            asm volatile("cp.async.wait_group 1;" ::: "memory");
        } else {
            asm volatile("cp.async.wait_group 0;" ::: "memory");
        }
        __syncthreads();

        const uint32_t Bs = bB + (ch & 1)*8192;
        const uint32_t Ach = (uint32_t)(ch*4096);
#pragma unroll
        for (int ks = 0; ks < 4; ks++){
            const int kc = ks*2;
            uint32_t afh[2][4], bfh[4];
#pragma unroll
            for (int mi = 0; mi < 2; mi++){
                const int row = mi*16 + (lane & 15);
                const int c = kc + (lane >> 4);
                ldsm4(afh[mi], aH + Ach + (uint32_t)(row*128 + ((c ^ (row & 7))*16)));
            }
            {
                const int row = w*16 + (lane & 15);
                const int c = kc + (lane >> 4);
                ldsm4(bfh, Bs + (uint32_t)(row*128 + ((c ^ (row & 7))*16)));
            }
#pragma unroll
            for (int mi = 0; mi < 2; mi++){
                mma16816(acc[mi][0], afh[mi], bfh[0], bfh[2]);
                mma16816(acc[mi][1], afh[mi], bfh[1], bfh[3]);
            }
        }
        __syncthreads();
    }

#pragma unroll
    for (int mi = 0; mi < 2; mi++)
#pragma unroll
        for (int n8 = 0; n8 < 2; n8++){
            const int b0 = mi*16 + (lane >> 2);
            const int oc = w*16 + n8*8 + (lane & 3)*2;
            const float bi0 = bias[n*64 + oc];
            const float bi1 = bias[n*64 + oc + 1];
            float2 v0, v1;
            v0.x = acc[mi][n8][0] + bi0; v0.y = acc[mi][n8][1] + bi1;
            v1.x = acc[mi][n8][2] + bi0; v1.y = acc[mi][n8][3] + bi1;
            *(float2*)(O + (long)n*2048 + b0*64 + oc)     = v0;
            *(float2*)(O + (long)n*2048 + (b0+8)*64 + oc) = v1;
        }
}

// ---------------- fp32 -> fp16 hi convert ----------------------------------
__global__ void conv_h(const float* __restrict__ in, __half* __restrict__ oh){
    int idx = blockIdx.x*256 + threadIdx.x;
    oh[idx] = __float2half_rn(in[idx]);
}

// ---------------- transpose, hi fp16 only ----------------------------------
__global__ void tsplit_h(const float* __restrict__ in, __half* __restrict__ oh,
                         int R, int Cc){
    __shared__ float t[32][33];
    int c0 = blockIdx.x*32, r0 = blockIdx.y*32;
    int tx = threadIdx.x, ty = threadIdx.y;
#pragma unroll
    for (int i = 0; i < 32; i += 8)
        t[ty+i][tx] = in[(long)(r0+ty+i)*Cc + c0+tx];
    __syncthreads();
#pragma unroll
    for (int i = 0; i < 32; i += 8)
        oh[(long)(c0+ty+i)*R + r0+tx] = __float2half_rn(t[tx][ty+i]);
}

// ---------------- row softmax of relu(row) -> fp16 hi plane ----------------
__global__ void relu_softmax_k(const float* __restrict__ in,
                               __half* __restrict__ oh){
    const int row = blockIdx.x;
    const int tid = threadIdx.x;
    __shared__ float rowv[1024];
    __shared__ float red[256];
    const float* r = in + (long)row*NN;
    for (int j=tid;j<NN;j+=256) rowv[j] = fmaxf(r[j], 0.f);
    __syncthreads();
    float mx = 0.f;
    for (int j=tid;j<NN;j+=256) mx = fmaxf(mx, rowv[j]);
    red[tid]=mx; __syncthreads();
    for (int s=128;s>0;s>>=1){ if(tid<s) red[tid]=fmaxf(red[tid],red[tid+s]); __syncthreads(); }
    mx = red[0];
    __syncthreads();
    float sum=0.f;
    for (int j=tid;j<NN;j+=256){ float e = expf(rowv[j]-mx); rowv[j]=e; sum+=e; }
    red[tid]=sum; __syncthreads();
    for (int s=128;s>0;s>>=1){ if(tid<s) red[tid]+=red[tid+s]; __syncthreads(); }
    float inv = 1.f/red[0];
    for (int j=tid;j<NN;j+=256)
        oh[(long)row*NN+j] = __float2half_rn(rowv[j]*inv);
}

// ---------------- x[B,N,T] -> X[N,B*T] fp32 + fp16 -------------------------
__global__ void txpose_x_k(const float* __restrict__ x, float* __restrict__ X,
                           __half* __restrict__ XH){
    int idx = blockIdx.x*256 + threadIdx.x;
    float4 v = ((const float4*)x)[((long)((idx>>4)&31)*NN + (idx>>9))*16 + (idx&15)];
    ((float4*)X)[idx] = v;
    uint2 p;
    p.x = packh2(v.x, v.y);
    p.y = packh2(v.z, v.w);
    *(uint2*)(XH + (long)idx*4) = p;
}

// ---------------- gather W -> Wmod [64, 20480], cols = o*320+ch*64+t -------
__global__ void wmod_k(const float* __restrict__ W, float* __restrict__ Wm){
    int idx = blockIdx.x*256 + threadIdx.x;
    if (idx >= DD*WCOLS) return;
    int d = idx / WCOLS;
    int c = idx - d*WCOLS;
    int o = c / 320;
    int r = c - o*320;
    int ch = r >> 6;
    int t = r & 63;
    int to = t*64 + o;
    float val;
    if (ch==0){
        val = W[(long)(d*3)*4096 + to] + W[(long)((64+d)*3)*4096 + to];
    } else {
        int g = (ch-1)&1;
        int k = 1 + ((ch-1)>>1);
        val = W[(long)((g*64+d)*3+k)*4096 + to];
    }
    Wm[idx] = val;
}

// ---------------- bias -----------------------------------------------------
__global__ void bias_k(const float* __restrict__ E, const float* __restrict__ bp,
                       float* __restrict__ bias){
    int n = blockIdx.x, o = threadIdx.x;
    float s = 0.f;
    for (int d=0; d<64; d++) s += E[n*64+d]*(bp[d*64+o] + bp[4096 + d*64+o]);
    bias[n*64+o]=s;
}

// ---------------- layer1 epilogue: LN/relu -> Xb fp32 + XH fp16 ------------
__global__ void proj_ln_relu_k(const float* __restrict__ O, const float* __restrict__ pw,
                               const float* __restrict__ pb, const float* __restrict__ gam,
                               const float* __restrict__ bet, float* __restrict__ Xout,
                               __half* __restrict__ XHout)
{
    const int nb = blockIdx.x;
    const int t = threadIdx.x;
    __shared__ float v[64], r1[64], r2[64];
    v[t] = O[(long)nb*64 + t];
    __syncthreads();
    float h = pb[t];
#pragma unroll
    for (int o=0;o<64;o++) h = fmaf(v[o], pw[o*64+t], h);
    r1[t]=h; r2[t]=h*h; __syncthreads();
    for (int s=32;s>0;s>>=1){ if(t<s){ r1[t]+=r1[t+s]; r2[t]+=r2[t+s]; } __syncthreads(); }
    float m = r1[0]*0.015625f;
    float var = r2[0]*0.015625f - m*m;
    float y = (h-m)*rsqrtf(var+1e-5f)*gam[t]+bet[t];
    y = fmaxf(y,0.f);
    const int n = nb>>5, b = nb&31;
    Xout[(long)n*BT + b*64 + t] = y;
    XHout[(long)n*BT + b*64 + t] = __float2half_rn(y);
}

// ---------------- layer2 epilogue ------------------------------------------
__global__ void final_k(const float* __restrict__ O, const float* __restrict__ pw,
                        const float* __restrict__ pb, const float* __restrict__ x,
                        const float* __restrict__ rg, const float* __restrict__ gam,
                        const float* __restrict__ bet, float* __restrict__ out)
{
    const int nb = blockIdx.x;
    const int t = threadIdx.x;
    const int n = nb>>5, b = nb&31;
    __shared__ float v[64], r1[64], r2[64];
    v[t]=O[(long)nb*64+t];
    __syncthreads();
    float h = pb[t];
#pragma unroll
    for (int o=0;o<64;o++) h = fmaf(v[o], pw[o*64+t], h);
    float sg = 1.f/(1.f+expf(-rg[0]));
    h = fmaf(sg, x[((long)b*NN+n)*64 + t], h);
    r1[t]=h; r2[t]=h*h; __syncthreads();
    for (int s=32;s>0;s>>=1){ if(t<s){ r1[t]+=r1[t+s]; r2[t]+=r2[t+s]; } __syncthreads(); }
    float m=r1[0]*0.015625f, var=r2[0]*0.015625f-m*m;
    out[((long)b*NN+n)*64+t] = (h-m)*rsqrtf(var+1e-5f)*gam[t]+bet[t];
}

// ===========================================================================
extern "C" void kernel_launch(void* const* d_in, const int* in_sizes, int n_in,
                              void* d_out, int out_size)
{
    const float* x     = (const float*)d_in[0];
    const float* A_fix = (const float*)d_in[1];
    const float* E     = (const float*)d_in[2];
    const float* W1    = (const float*)d_in[3];
    const float* b1p   = (const float*)d_in[4];
    const float* W2    = (const float*)d_in[5];
    const float* b2p   = (const float*)d_in[6];
    const float* p1w   = (const float*)d_in[7];
    const float* p1b   = (const float*)d_in[8];
    const float* p2w   = (const float*)d_in[9];
    const float* p2b   = (const float*)d_in[10];
    const float* g1    = (const float*)d_in[11];
    const float* be1   = (const float*)d_in[12];
    const float* g2    = (const float*)d_in[13];
    const float* be2   = (const float*)d_in[14];
    const float* rg    = (const float*)d_in[15];
    float* out = (float*)d_out;

    float *Xb,*Wm,*Ob,*Bi;
    __half *XH,*YH,*SH,*BH,*YTH,*EH,*WTH,*WbH;
    cudaGetSymbolAddress((void**)&Xb,  g_Xbuf);
    cudaGetSymbolAddress((void**)&Wm,  g_Wmod);
    cudaGetSymbolAddress((void**)&Ob,  g_Obuf);
    cudaGetSymbolAddress((void**)&Bi,  g_bias);
    cudaGetSymbolAddress((void**)&XH,  g_XH);
    cudaGetSymbolAddress((void**)&YH,  g_YH);
    cudaGetSymbolAddress((void**)&SH,  g_SH);
    cudaGetSymbolAddress((void**)&BH,  g_BH);
    cudaGetSymbolAddress((void**)&YTH, g_YTH);
    cudaGetSymbolAddress((void**)&EH,  g_EH);
    cudaGetSymbolAddress((void**)&WTH, g_WTH);
    cudaGetSymbolAddress((void**)&WbH, g_WbH);

    cudaFuncSetAttribute(gemm_mma_k, cudaFuncAttributeMaxDynamicSharedMemorySize, 98304);
    cudaFuncSetAttribute(contract_mma_k, cudaFuncAttributeMaxDynamicSharedMemorySize, 36864);
    const int MMSM = 98304;
    const int CTSM = 36864;

    // --- prologue ---
    wmod_k<<<(DD*WCOLS+255)/256,256>>>(W1, Wm);
    tsplit_h<<<dim3(640,2,1),dim3(32,8)>>>(Wm, WTH, 64, WCOLS);
    conv_h<<<(NN*DD)/256,256>>>(E, EH);
    gemm_mma_k<<<dim3(160,8,1),256,MMSM>>>(EH, WTH, nullptr, nullptr, 1.f,
                                           64, 1, WCOLS, 0, 0, 0,
                                           nullptr, WbH);
    gemm_mma_k<<<dim3(8,8,1),256,MMSM>>>(EH, EH, Ob, nullptr, 1.f,
                                         64, 1, 1024, 0, 0, 0,
                                         nullptr, nullptr);
    relu_softmax_k<<<1024,256>>>(Ob,    SH);
    relu_softmax_k<<<1024,256>>>(A_fix, SH + (long)NN*NN);
    txpose_x_k<<<2048,256>>>(x, Xb, XH);
    tsplit_h<<<dim3(64,32,1),dim3(32,8)>>>(Xb, BH, 1024, 2048);
    bias_k<<<1024,64>>>(E, b1p, Bi);

    // --- layer 1 ---
    gemm_mma_k<<<dim3(16,16,1),256,MMSM>>>(SH, BH, nullptr, nullptr, 1.f,
                                           1024, 16, 2048, 0, 0, 0,
                                           YTH, YH);
    gemm_mma_k<<<dim3(16,8,2),256,MMSM>>>(SH, YTH, nullptr, Xb, 2.f,
                                          1024, 16, 2048, 1024, 2048L*1024, 1024L*2048,
                                          nullptr, YH + 2L*NN*BT);
    contract_mma_k<<<1024,128,CTSM>>>(XH, YH, WbH, Bi, Ob);
    proj_ln_relu_k<<<NN*BB,64>>>(Ob, p1w, p1b, g1, be1, Xb, XH);

    // --- layer 2 ---
    wmod_k<<<(DD*WCOLS+255)/256,256>>>(W2, Wm);
    tsplit_h<<<dim3(640,2,1),dim3(32,8)>>>(Wm, WTH, 64, WCOLS);
    gemm_mma_k<<<dim3(160,8,1),256,MMSM>>>(EH, WTH, nullptr, nullptr, 1.f,
                                           64, 1, WCOLS, 0, 0, 0,
                                           nullptr, WbH);
    bias_k<<<1024,64>>>(E, b2p, Bi);
    tsplit_h<<<dim3(64,32,1),dim3(32,8)>>>(Xb, BH, 1024, 2048);
    gemm_mma_k<<<dim3(16,16,1),256,MMSM>>>(SH, BH, nullptr, nullptr, 1.f,
                                           1024, 16, 2048, 0, 0, 0,
                                           YTH, YH);
    gemm_mma_k<<<dim3(16,8,2),256,MMSM>>>(SH, YTH, nullptr, Xb, 2.f,
                                          1024, 16, 2048, 1024, 2048L*1024, 1024L*2048,
                                          nullptr, YH + 2L*NN*BT);
    contract_mma_k<<<1024,128,CTSM>>>(XH, YH, WbH, Bi, Ob);
    final_k<<<NN*BB,64>>>(Ob, p2w, p2b, x, rg, g2, be2, out);
}